// round 1
// baseline (speedup 1.0000x reference)
#include <cuda_runtime.h>

// Problem constants (fixed by reference setup_inputs)
#define C_CLS 256
#define S_SUP 5
#define Q_QRY 64
#define DIN   1024
#define ZD    128
#define CS    (C_CLS*S_SUP)              // 1280
#define CQ    (C_CLS*Q_QRY)              // 16384
#define M_TOT (CS+CQ)                    // 17664
#define NPAIRS (C_CLS*(Q_QRY*(Q_QRY-1)/2)) // 516096
#define EPSF  1e-8f

typedef unsigned long long u64;

// ---------------- device scratch (no allocations allowed) ----------------
__device__ __align__(16) float g_z[(size_t)M_TOT * ZD];        // ~9 MB
__device__ __align__(16) float g_protoT[ZD * C_CLS];           // proto transposed [k][c]
__device__ float g_proto2[C_CLS];                              // ||proto_c||^2
__device__ float g_cos_sum;
__device__ float g_acc_cnt;

// ---------------- packed fp32x2 helpers (Blackwell FFMA2) ----------------
__device__ __forceinline__ u64 pack2(float x, float y){
    u64 r; asm("mov.b64 %0, {%1, %2};" : "=l"(r) : "f"(x), "f"(y)); return r;
}
__device__ __forceinline__ void fma2(u64 &d, u64 a, u64 b){
    asm("fma.rn.f32x2 %0, %1, %2, %0;" : "+l"(d) : "l"(a), "l"(b));
}
__device__ __forceinline__ float2 unpack2(u64 v){
    float lo, hi; asm("mov.b64 {%0, %1}, %2;" : "=f"(lo), "=f"(hi) : "l"(v));
    return make_float2(lo, hi);
}

// ---------------- K0: reset accumulators (graph replays) ----------------
__global__ void k_init(){
    g_cos_sum = 0.0f;
    g_acc_cnt = 0.0f;
}

// ---------------- K1: z = [xs; xq] @ W  (fp32, FFMA2 inner loop) ----------
// Grid: 138 blocks (17664/128), Block: 256 threads (16x16), tile 128x128, BK=16.
// A stored in SMEM pre-duplicated as (a,a) f32x2 pairs -> inner loop is
// 8 LDS.64 (A dup) + 4 LDS.64 (B pair) + 32 FFMA2 per k-step per thread.
#define BK 16
__global__ __launch_bounds__(256) void k_gemm(const float* __restrict__ xs,
                                              const float* __restrict__ xq,
                                              const float* __restrict__ W){
    __shared__ u64 As2[2][BK][128];                    // 32 KB
    __shared__ __align__(16) float Bs[2][BK][128];     // 16 KB  (total 48 KB)
    const int tid = threadIdx.x;
    const int tx = tid & 15, ty = tid >> 4;
    const int bm = blockIdx.x;
    const float* X = (bm < 10) ? (xs + (size_t)bm * (128 * DIN))
                               : (xq + (size_t)(bm - 10) * (128 * DIN));
    const int lm = tid >> 2;            // A row within tile (0..63), +64 for second
    const int lk = (tid & 3) << 2;      // A k chunk base (0,4,8,12)
    const int bk = tid >> 5;            // B k row (0..7), +8 for second
    const int bn = (tid & 31) << 2;     // B n chunk base

    u64 acc[8][4];
#pragma unroll
    for (int i = 0; i < 8; i++)
#pragma unroll
        for (int j = 0; j < 4; j++) acc[i][j] = 0ull;

    float4 a0, a1, b0, b1;
    // preload tile 0
    a0 = *(const float4*)(X + (size_t)lm * DIN + lk);
    a1 = *(const float4*)(X + (size_t)(lm + 64) * DIN + lk);
    b0 = *(const float4*)(W + (size_t)bk * ZD + bn);
    b1 = *(const float4*)(W + (size_t)(bk + 8) * ZD + bn);
    As2[0][lk + 0][lm]      = pack2(a0.x, a0.x);
    As2[0][lk + 1][lm]      = pack2(a0.y, a0.y);
    As2[0][lk + 2][lm]      = pack2(a0.z, a0.z);
    As2[0][lk + 3][lm]      = pack2(a0.w, a0.w);
    As2[0][lk + 0][lm + 64] = pack2(a1.x, a1.x);
    As2[0][lk + 1][lm + 64] = pack2(a1.y, a1.y);
    As2[0][lk + 2][lm + 64] = pack2(a1.z, a1.z);
    As2[0][lk + 3][lm + 64] = pack2(a1.w, a1.w);
    *(float4*)&Bs[0][bk][bn]     = b0;
    *(float4*)&Bs[0][bk + 8][bn] = b1;
    __syncthreads();

    int buf = 0;
    const int nT = DIN / BK;   // 64
    for (int kt = 0; kt < nT; kt++){
        if (kt + 1 < nT){
            const int kb = (kt + 1) * BK;
            a0 = *(const float4*)(X + (size_t)lm * DIN + kb + lk);
            a1 = *(const float4*)(X + (size_t)(lm + 64) * DIN + kb + lk);
            b0 = *(const float4*)(W + (size_t)(kb + bk) * ZD + bn);
            b1 = *(const float4*)(W + (size_t)(kb + bk + 8) * ZD + bn);
        }
#pragma unroll
        for (int k = 0; k < BK; k++){
            u64 ad[8], bp[4];
            const u64* arow = &As2[buf][k][ty * 8];
            const u64* brow = (const u64*)&Bs[buf][k][tx * 8];
#pragma unroll
            for (int i = 0; i < 8; i++) ad[i] = arow[i];
#pragma unroll
            for (int j = 0; j < 4; j++) bp[j] = brow[j];
#pragma unroll
            for (int i = 0; i < 8; i++)
#pragma unroll
                for (int j = 0; j < 4; j++) fma2(acc[i][j], ad[i], bp[j]);
        }
        if (kt + 1 < nT){
            const int nb = buf ^ 1;
            As2[nb][lk + 0][lm]      = pack2(a0.x, a0.x);
            As2[nb][lk + 1][lm]      = pack2(a0.y, a0.y);
            As2[nb][lk + 2][lm]      = pack2(a0.z, a0.z);
            As2[nb][lk + 3][lm]      = pack2(a0.w, a0.w);
            As2[nb][lk + 0][lm + 64] = pack2(a1.x, a1.x);
            As2[nb][lk + 1][lm + 64] = pack2(a1.y, a1.y);
            As2[nb][lk + 2][lm + 64] = pack2(a1.z, a1.z);
            As2[nb][lk + 3][lm + 64] = pack2(a1.w, a1.w);
            *(float4*)&Bs[nb][bk][bn]     = b0;
            *(float4*)&Bs[nb][bk + 8][bn] = b1;
            __syncthreads();
            buf = nb;
        }
    }
    const size_t rb = (size_t)bm * 128;
#pragma unroll
    for (int i = 0; i < 8; i++){
        ulonglong2* o2 = (ulonglong2*)(g_z + (rb + ty * 8 + i) * ZD + tx * 8);
        o2[0] = make_ulonglong2(acc[i][0], acc[i][1]);
        o2[1] = make_ulonglong2(acc[i][2], acc[i][3]);
    }
}

// ---------------- K2: prototypes (mean over S=5) + ||proto||^2 -----------
__global__ __launch_bounds__(128) void k_proto(){
    const int c = blockIdx.x;
    const int d = threadIdx.x;  // 0..127
    const float* z = g_z + (size_t)c * S_SUP * ZD + d;
    float p = 0.0f;
#pragma unroll
    for (int s = 0; s < S_SUP; s++) p += z[s * ZD];
    p *= (1.0f / S_SUP);
    g_protoT[d * C_CLS + c] = p;             // transposed for K3 coalesced loads
    float sq = p * p;
#pragma unroll
    for (int off = 16; off; off >>= 1) sq += __shfl_xor_sync(0xffffffffu, sq, off);
    __shared__ float w[4];
    if ((d & 31) == 0) w[d >> 5] = sq;
    __syncthreads();
    if (d == 0) g_proto2[c] = w[0] + w[1] + w[2] + w[3];
}

// ---------------- K3: per-class fused d2 + loo-norm + cos + argmin -------
// One block per class. d2 (64x256) lives in registers via a 64x256x128
// FFMA2 GEMM against protoT (full 128KB proto in SMEM; reused 256x -> L2 hot).
// cos identity: sum_{q<k} a_q.a_k = ( ||sum_q a_q||^2 - sum_q ||a_q||^2 ) / 2.
__global__ __launch_bounds__(256) void k_class(){
    extern __shared__ float sm[];
    float* protoT = sm;                 // [128][256] = 32768 floats
    float* zqT    = sm + 32768;         // [128][64]  =  8192 floats
    float* s_acc  = zqT + 8192;         // [256] per-class sum of a-vectors
    float* pn2    = s_acc + 256;        // [256]
    float* qn2    = pn2 + 256;          // [64]
    float* red    = qn2 + 64;           // [64] scratch: [0]=sumA2 [1]=acc [2..9]=warp sums

    const int tid = threadIdx.x;
    const int c   = blockIdx.x;
    const int tx  = tid & 15, ty = tid >> 4;

    // load protoT (coalesced, conflict-free stores)
    for (int f = tid; f < 8192; f += 256){
        const int k  = f >> 6;
        const int p0 = (f & 63) << 2;
        *(float4*)&protoT[k * 256 + p0] = *(const float4*)&g_protoT[k * 256 + p0];
    }
    // load zq for this class, transposed into zqT[k][q]
    const float* zq = g_z + (size_t)(CS + c * Q_QRY) * ZD;
    for (int f = tid; f < 2048; f += 256){
        const int q  = f & 63;
        const int k0 = (f >> 6) << 2;
        float4 v = *(const float4*)&zq[q * ZD + k0];
        zqT[(k0 + 0) * 64 + q] = v.x;
        zqT[(k0 + 1) * 64 + q] = v.y;
        zqT[(k0 + 2) * 64 + q] = v.z;
        zqT[(k0 + 3) * 64 + q] = v.w;
    }
    pn2[tid]   = g_proto2[tid];
    s_acc[tid] = 0.0f;
    if (tid == 0){ red[0] = 0.0f; red[1] = 0.0f; }
    __syncthreads();

    // ||zq_q||^2
    if (tid < 64){
        float ss = 0.0f;
        for (int k = 0; k < ZD; k++){ float v = zqT[k * 64 + tid]; ss = fmaf(v, v, ss); }
        qn2[tid] = ss;
    }
    __syncthreads();

    // phase 1: dot(zq_q, proto_p) in registers; thread owns 4 q x 16 p (as 8 pairs)
    u64 acc2[4][8];
#pragma unroll
    for (int i = 0; i < 4; i++)
#pragma unroll
        for (int j = 0; j < 8; j++) acc2[i][j] = 0ull;

    for (int k = 0; k < ZD; k++){
        u64 bp[8];
        const u64* prow = (const u64*)&protoT[k * 256 + tx * 16];
#pragma unroll
        for (int j = 0; j < 8; j++) bp[j] = prow[j];
#pragma unroll
        for (int i = 0; i < 4; i++){
            const float a = zqT[k * 64 + ty * 4 + i];
            const u64 ap = pack2(a, a);
#pragma unroll
            for (int j = 0; j < 8; j++) fma2(acc2[i][j], ap, bp[j]);
        }
    }

    // d2 = qn2 + pn2 - 2*dot
    float d2r[4][16];
    float qn[4], pn[16];
#pragma unroll
    for (int i = 0; i < 4; i++) qn[i] = qn2[ty * 4 + i];
#pragma unroll
    for (int j = 0; j < 16; j++) pn[j] = pn2[tx * 16 + j];
#pragma unroll
    for (int i = 0; i < 4; i++)
#pragma unroll
        for (int j2 = 0; j2 < 8; j2++){
            float2 f = unpack2(acc2[i][j2]);
            d2r[i][2 * j2]     = qn[i] + pn[2 * j2]     - 2.0f * f.x;
            d2r[i][2 * j2 + 1] = qn[i] + pn[2 * j2 + 1] - 2.0f * f.y;
        }

    // phase 2: per row (16 lanes with same ty hold one row's 256 values)
#pragma unroll
    for (int i = 0; i < 4; i++){
        float sumsq = 0.0f;
        float minv  = 3.4e38f;
        int   mini  = 0x7fffffff;
#pragma unroll
        for (int j = 0; j < 16; j++){
            const int p = tx * 16 + j;
            const float v = d2r[i][j];
            if (p != c) sumsq = fmaf(v, v, sumsq);
            if (v < minv || (v == minv && p < mini)){ minv = v; mini = p; }
        }
        // reduce across the 16-lane group (xor <=8 stays within halves)
#pragma unroll
        for (int off = 8; off; off >>= 1){
            sumsq += __shfl_xor_sync(0xffffffffu, sumsq, off);
            const float ov = __shfl_xor_sync(0xffffffffu, minv, off);
            const int   oi = __shfl_xor_sync(0xffffffffu, mini, off);
            if (ov < minv || (ov == minv && oi < mini)){ minv = ov; mini = oi; }
        }
        const float nrm = fmaxf(sqrtf(sumsq), EPSF);
        const float inv = 1.0f / nrm;
#pragma unroll
        for (int j = 0; j < 16; j++){
            const int p = tx * 16 + j;
            if (p != c) atomicAdd(&s_acc[p], d2r[i][j] * inv);
        }
        if (tx == 0){
            atomicAdd(&red[0], sumsq * inv * inv);          // sum_q ||a_q||^2
            if (mini == c) atomicAdd(&red[1], 1.0f);        // correct argmin
        }
    }
    __syncthreads();

    // ||sum_q a_q||^2
    float v = s_acc[tid]; v = v * v;
#pragma unroll
    for (int off = 16; off; off >>= 1) v += __shfl_xor_sync(0xffffffffu, v, off);
    if ((tid & 31) == 0) red[2 + (tid >> 5)] = v;
    __syncthreads();
    if (tid == 0){
        float ss = 0.0f;
#pragma unroll
        for (int w = 0; w < 8; w++) ss += red[2 + w];
        const float cosc = 0.5f * (ss - red[0]);
        atomicAdd(&g_cos_sum, cosc);
        atomicAdd(&g_acc_cnt, red[1]);
    }
}

// ---------------- K4: finalize -------------------------------------------
__global__ void k_final(float* __restrict__ out){
    if (threadIdx.x == 0){
        out[0] = g_cos_sum / (float)NPAIRS;
        out[1] = g_acc_cnt / (float)CQ;
    }
}

// ---------------- launch ---------------------------------------------------
extern "C" void kernel_launch(void* const* d_in, const int* in_sizes, int n_in,
                              void* d_out, int out_size){
    const float* xs = (const float*)d_in[0];
    const float* xq = (const float*)d_in[1];
    const float* W  = (const float*)d_in[2];
    float* out = (float*)d_out;
    (void)in_sizes; (void)n_in; (void)out_size;

    const int smem_class = (32768 + 8192 + 256 + 256 + 64 + 64) * (int)sizeof(float);
    cudaFuncSetAttribute(k_class, cudaFuncAttributeMaxDynamicSharedMemorySize, smem_class);

    k_init<<<1, 1>>>();
    k_gemm<<<M_TOT / 128, 256>>>(xs, xq, W);
    k_proto<<<C_CLS, 128>>>();
    k_class<<<C_CLS, 256, smem_class>>>();
    k_final<<<1, 1>>>(out);
}

// round 2
// speedup vs baseline: 1.5954x; 1.5954x over previous
#include <cuda_runtime.h>

// Problem constants (fixed by reference setup_inputs)
#define C_CLS 256
#define S_SUP 5
#define Q_QRY 64
#define DIN   1024
#define ZD    128
#define CS    (C_CLS*S_SUP)              // 1280
#define CQ    (C_CLS*Q_QRY)              // 16384
#define M_TOT (CS+CQ)                    // 17664
#define NPAIRS (C_CLS*(Q_QRY*(Q_QRY-1)/2)) // 516096
#define EPSF  1e-8f

typedef unsigned long long u64;

// ---------------- device scratch (no allocations allowed) ----------------
__device__ __align__(16) float g_z[(size_t)M_TOT * ZD];        // ~9 MB
__device__ __align__(16) float g_d2[(size_t)CQ * C_CLS];       // 16 MB
__device__ __align__(16) float g_protoT[ZD * C_CLS];           // [k][c]
__device__ __align__(16) float g_proto2[C_CLS];                // ||proto_c||^2
__device__ __align__(16) float g_row2[M_TOT];                  // ||z_row||^2
__device__ float g_cos_sum;
__device__ float g_acc_cnt;

// ---------------- packed fp32x2 helpers (Blackwell FFMA2) ----------------
__device__ __forceinline__ u64 pack2(float x, float y){
    u64 r; asm("mov.b64 %0, {%1, %2};" : "=l"(r) : "f"(x), "f"(y)); return r;
}
__device__ __forceinline__ void fma2(u64 &d, u64 a, u64 b){
    asm("fma.rn.f32x2 %0, %1, %2, %0;" : "+l"(d) : "l"(a), "l"(b));
}
__device__ __forceinline__ float2 unpack2(u64 v){
    float lo, hi; asm("mov.b64 {%0, %1}, %2;" : "=f"(lo), "=f"(hi) : "l"(v));
    return make_float2(lo, hi);
}

// ---------------- K0: reset accumulators (graph replays) ----------------
__global__ void k_init(){
    g_cos_sum = 0.0f;
    g_acc_cnt = 0.0f;
}

// =====================================================================
// K1: z = [xs; xq] @ W   (M=17664, K=1024, N=128), fp32 FFMA2.
// Tile 128x128, BK=16, 256 threads. Thread (tx,ty) owns rows ty*8..+7,
// cols {4tx..4tx+3} u {64+4tx..+3}  -> B loads are DENSE 256B LDS.128
// wavefronts (no bank conflicts), B f32x2 pairs are memory-adjacent.
// Epilogue fuses per-row ||z||^2 into g_row2.
// =====================================================================
#define BK 16
__global__ __launch_bounds__(256) void k_gemm(const float* __restrict__ xs,
                                              const float* __restrict__ xq,
                                              const float* __restrict__ W){
    __shared__ __align__(16) u64   As2[2][BK][128];   // A duplicated (a,a): 32 KB
    __shared__ __align__(16) float Bs [2][BK][128];   // 16 KB  (total 48 KB exactly)
    const int tid = threadIdx.x;
    const int tx = tid & 15, ty = tid >> 4;
    const int bm = blockIdx.x;
    const float* X = (bm < 10) ? (xs + (size_t)bm * (128 * DIN))
                               : (xq + (size_t)(bm - 10) * (128 * DIN));
    const int lm = tid >> 2;            // A row (0..63, +64)
    const int lk = (tid & 3) << 2;      // A k chunk
    const int bk = tid >> 5;            // B k row (0..7, +8)
    const int bn = (tid & 31) << 2;     // B n chunk

    u64 acc[8][4];
#pragma unroll
    for (int i = 0; i < 8; i++)
#pragma unroll
        for (int j = 0; j < 4; j++) acc[i][j] = 0ull;

    float4 a0, a1, b0, b1;
    a0 = *(const float4*)(X + (size_t)lm * DIN + lk);
    a1 = *(const float4*)(X + (size_t)(lm + 64) * DIN + lk);
    b0 = *(const float4*)(W + (size_t)bk * ZD + bn);
    b1 = *(const float4*)(W + (size_t)(bk + 8) * ZD + bn);
    As2[0][lk + 0][lm]      = pack2(a0.x, a0.x);
    As2[0][lk + 1][lm]      = pack2(a0.y, a0.y);
    As2[0][lk + 2][lm]      = pack2(a0.z, a0.z);
    As2[0][lk + 3][lm]      = pack2(a0.w, a0.w);
    As2[0][lk + 0][lm + 64] = pack2(a1.x, a1.x);
    As2[0][lk + 1][lm + 64] = pack2(a1.y, a1.y);
    As2[0][lk + 2][lm + 64] = pack2(a1.z, a1.z);
    As2[0][lk + 3][lm + 64] = pack2(a1.w, a1.w);
    *(float4*)&Bs[0][bk][bn]     = b0;
    *(float4*)&Bs[0][bk + 8][bn] = b1;
    __syncthreads();

    int buf = 0;
    const int nT = DIN / BK;   // 64
    for (int kt = 0; kt < nT; kt++){
        if (kt + 1 < nT){
            const int kb = (kt + 1) * BK;
            a0 = *(const float4*)(X + (size_t)lm * DIN + kb + lk);
            a1 = *(const float4*)(X + (size_t)(lm + 64) * DIN + kb + lk);
            b0 = *(const float4*)(W + (size_t)(kb + bk) * ZD + bn);
            b1 = *(const float4*)(W + (size_t)(kb + bk + 8) * ZD + bn);
        }
#pragma unroll
        for (int k = 0; k < BK; k++){
            const ulonglong2 aA = *(const ulonglong2*)&As2[buf][k][ty * 8 + 0];
            const ulonglong2 aB = *(const ulonglong2*)&As2[buf][k][ty * 8 + 2];
            const ulonglong2 aC = *(const ulonglong2*)&As2[buf][k][ty * 8 + 4];
            const ulonglong2 aD = *(const ulonglong2*)&As2[buf][k][ty * 8 + 6];
            const ulonglong2 bL = *(const ulonglong2*)&Bs[buf][k][tx * 4];       // cols 4tx..+3
            const ulonglong2 bH = *(const ulonglong2*)&Bs[buf][k][64 + tx * 4];  // cols 64+4tx..+3
            const u64 av[8] = {aA.x, aA.y, aB.x, aB.y, aC.x, aC.y, aD.x, aD.y};
#pragma unroll
            for (int i = 0; i < 8; i++){
                fma2(acc[i][0], av[i], bL.x);
                fma2(acc[i][1], av[i], bL.y);
                fma2(acc[i][2], av[i], bH.x);
                fma2(acc[i][3], av[i], bH.y);
            }
        }
        if (kt + 1 < nT){
            const int nb = buf ^ 1;
            As2[nb][lk + 0][lm]      = pack2(a0.x, a0.x);
            As2[nb][lk + 1][lm]      = pack2(a0.y, a0.y);
            As2[nb][lk + 2][lm]      = pack2(a0.z, a0.z);
            As2[nb][lk + 3][lm]      = pack2(a0.w, a0.w);
            As2[nb][lk + 0][lm + 64] = pack2(a1.x, a1.x);
            As2[nb][lk + 1][lm + 64] = pack2(a1.y, a1.y);
            As2[nb][lk + 2][lm + 64] = pack2(a1.z, a1.z);
            As2[nb][lk + 3][lm + 64] = pack2(a1.w, a1.w);
            *(float4*)&Bs[nb][bk][bn]     = b0;
            *(float4*)&Bs[nb][bk + 8][bn] = b1;
            __syncthreads();
            buf = nb;
        }
    }

    // epilogue: store z, fuse row norms (16 tx lanes cover all 128 cols)
    const size_t rb = (size_t)bm * 128;
#pragma unroll
    for (int i = 0; i < 8; i++){
        float s = 0.0f;
#pragma unroll
        for (int j = 0; j < 4; j++){
            const float2 f = unpack2(acc[i][j]);
            s = fmaf(f.x, f.x, s);
            s = fmaf(f.y, f.y, s);
        }
#pragma unroll
        for (int off = 1; off <= 8; off <<= 1)
            s += __shfl_xor_sync(0xffffffffu, s, off);
        const size_t row = rb + ty * 8 + i;
        if (tx == 0) g_row2[row] = s;
        float* zr = g_z + row * ZD;
        *(ulonglong2*)(zr + 4 * tx)      = make_ulonglong2(acc[i][0], acc[i][1]);
        *(ulonglong2*)(zr + 64 + 4 * tx) = make_ulonglong2(acc[i][2], acc[i][3]);
    }
}

// ---------------- K2: prototypes (mean over S=5) + ||proto||^2 -----------
__global__ __launch_bounds__(128) void k_proto(){
    const int c = blockIdx.x;
    const int d = threadIdx.x;  // 0..127
    const float* z = g_z + (size_t)c * S_SUP * ZD + d;
    float p = 0.0f;
#pragma unroll
    for (int s = 0; s < S_SUP; s++) p += z[s * ZD];
    p *= (1.0f / S_SUP);
    g_protoT[d * C_CLS + c] = p;
    float sq = p * p;
#pragma unroll
    for (int off = 16; off; off >>= 1) sq += __shfl_xor_sync(0xffffffffu, sq, off);
    __shared__ float w[4];
    if ((d & 31) == 0) w[d >> 5] = sq;
    __syncthreads();
    if (d == 0) g_proto2[c] = w[0] + w[1] + w[2] + w[3];
}

// =====================================================================
// K3: d2 = ||zq||^2 + ||proto||^2 - 2 zq@protoT  (16384 x 256 x 128 GEMM)
// Same fixed-bank tile structure as K1. Grid (128, 2). Writes g_d2.
// =====================================================================
__global__ __launch_bounds__(256) void k_d2(){
    __shared__ __align__(16) u64   As2[2][BK][128];
    __shared__ __align__(16) float Bs [2][BK][128];
    const int tid = threadIdx.x;
    const int tx = tid & 15, ty = tid >> 4;
    const int qb = blockIdx.x;          // 0..127 (query tiles)
    const int cb = blockIdx.y;          // 0..1   (proto tiles)
    const float* A  = g_z + (size_t)(CS + qb * 128) * ZD;
    const float* Bp = g_protoT + cb * 128;
    const int lm = tid >> 2, lk = (tid & 3) << 2;
    const int bk = tid >> 5, bn = (tid & 31) << 2;

    u64 acc[8][4];
#pragma unroll
    for (int i = 0; i < 8; i++)
#pragma unroll
        for (int j = 0; j < 4; j++) acc[i][j] = 0ull;

    float4 a0, a1, b0, b1;
    a0 = *(const float4*)(A + (size_t)lm * ZD + lk);
    a1 = *(const float4*)(A + (size_t)(lm + 64) * ZD + lk);
    b0 = *(const float4*)(Bp + (size_t)bk * C_CLS + bn);
    b1 = *(const float4*)(Bp + (size_t)(bk + 8) * C_CLS + bn);
    As2[0][lk + 0][lm]      = pack2(a0.x, a0.x);
    As2[0][lk + 1][lm]      = pack2(a0.y, a0.y);
    As2[0][lk + 2][lm]      = pack2(a0.z, a0.z);
    As2[0][lk + 3][lm]      = pack2(a0.w, a0.w);
    As2[0][lk + 0][lm + 64] = pack2(a1.x, a1.x);
    As2[0][lk + 1][lm + 64] = pack2(a1.y, a1.y);
    As2[0][lk + 2][lm + 64] = pack2(a1.z, a1.z);
    As2[0][lk + 3][lm + 64] = pack2(a1.w, a1.w);
    *(float4*)&Bs[0][bk][bn]     = b0;
    *(float4*)&Bs[0][bk + 8][bn] = b1;
    __syncthreads();

    int buf = 0;
    const int nT = ZD / BK;   // 8
    for (int kt = 0; kt < nT; kt++){
        if (kt + 1 < nT){
            const int kb = (kt + 1) * BK;
            a0 = *(const float4*)(A + (size_t)lm * ZD + kb + lk);
            a1 = *(const float4*)(A + (size_t)(lm + 64) * ZD + kb + lk);
            b0 = *(const float4*)(Bp + (size_t)(kb + bk) * C_CLS + bn);
            b1 = *(const float4*)(Bp + (size_t)(kb + bk + 8) * C_CLS + bn);
        }
#pragma unroll
        for (int k = 0; k < BK; k++){
            const ulonglong2 aA = *(const ulonglong2*)&As2[buf][k][ty * 8 + 0];
            const ulonglong2 aB = *(const ulonglong2*)&As2[buf][k][ty * 8 + 2];
            const ulonglong2 aC = *(const ulonglong2*)&As2[buf][k][ty * 8 + 4];
            const ulonglong2 aD = *(const ulonglong2*)&As2[buf][k][ty * 8 + 6];
            const ulonglong2 bL = *(const ulonglong2*)&Bs[buf][k][tx * 4];
            const ulonglong2 bH = *(const ulonglong2*)&Bs[buf][k][64 + tx * 4];
            const u64 av[8] = {aA.x, aA.y, aB.x, aB.y, aC.x, aC.y, aD.x, aD.y};
#pragma unroll
            for (int i = 0; i < 8; i++){
                fma2(acc[i][0], av[i], bL.x);
                fma2(acc[i][1], av[i], bL.y);
                fma2(acc[i][2], av[i], bH.x);
                fma2(acc[i][3], av[i], bH.y);
            }
        }
        if (kt + 1 < nT){
            const int nb = buf ^ 1;
            As2[nb][lk + 0][lm]      = pack2(a0.x, a0.x);
            As2[nb][lk + 1][lm]      = pack2(a0.y, a0.y);
            As2[nb][lk + 2][lm]      = pack2(a0.z, a0.z);
            As2[nb][lk + 3][lm]      = pack2(a0.w, a0.w);
            As2[nb][lk + 0][lm + 64] = pack2(a1.x, a1.x);
            As2[nb][lk + 1][lm + 64] = pack2(a1.y, a1.y);
            As2[nb][lk + 2][lm + 64] = pack2(a1.z, a1.z);
            As2[nb][lk + 3][lm + 64] = pack2(a1.w, a1.w);
            *(float4*)&Bs[nb][bk][bn]     = b0;
            *(float4*)&Bs[nb][bk + 8][bn] = b1;
            __syncthreads();
            buf = nb;
        }
    }

    // epilogue: d2 = qn + pn - 2*dot   (qn/pn via L2-hot LDG)
    const float4 pL = *(const float4*)&g_proto2[cb * 128 + 4 * tx];
    const float4 pH = *(const float4*)&g_proto2[cb * 128 + 64 + 4 * tx];
#pragma unroll
    for (int i = 0; i < 8; i++){
        const int row = qb * 128 + ty * 8 + i;
        const float qn = g_row2[CS + row];
        float2 f0 = unpack2(acc[i][0]);
        float2 f1 = unpack2(acc[i][1]);
        float2 f2 = unpack2(acc[i][2]);
        float2 f3 = unpack2(acc[i][3]);
        float4 dL = make_float4(qn + pL.x - 2.0f * f0.x, qn + pL.y - 2.0f * f0.y,
                                qn + pL.z - 2.0f * f1.x, qn + pL.w - 2.0f * f1.y);
        float4 dH = make_float4(qn + pH.x - 2.0f * f2.x, qn + pH.y - 2.0f * f2.y,
                                qn + pH.z - 2.0f * f3.x, qn + pH.w - 2.0f * f3.y);
        float* dr = g_d2 + (size_t)row * C_CLS + cb * 128;
        *(float4*)(dr + 4 * tx)      = dL;
        *(float4*)(dr + 64 + 4 * tx) = dH;
    }
}

// =====================================================================
// K4: per-class loo-norm + cos identity + argmin. One block per class,
// 8 warps x 8 query rows, lane owns 8 proto columns. All register-resident,
// no spills, no cross-warp atomics for the a-sum (staged 8x256 smem).
// cos: sum_{q<k} a_q.a_k = ( ||sum_q a_q||^2 - sum_q ||a_q||^2 ) / 2
// =====================================================================
__global__ __launch_bounds__(256) void k_loo(){
    __shared__ float s_part[8][256];   // per-warp partial a-sums
    __shared__ float s_red[8];
    __shared__ float s_scal[2];        // [0]=sum||a||^2, [1]=correct count

    const int tid  = threadIdx.x;
    const int c    = blockIdx.x;
    const int w    = tid >> 5;
    const int lane = tid & 31;
    if (tid < 2) s_scal[tid] = 0.0f;
    __syncthreads();

    // load this warp's 8 rows x 8 cols of d2 into registers (16x LDG.128)
    const float* D = g_d2 + ((size_t)c * Q_QRY + w * 8) * C_CLS + lane * 8;
    float d2v[8][8];
#pragma unroll
    for (int r = 0; r < 8; r++){
        const float4 v0 = *(const float4*)(D + (size_t)r * C_CLS);
        const float4 v1 = *(const float4*)(D + (size_t)r * C_CLS + 4);
        d2v[r][0] = v0.x; d2v[r][1] = v0.y; d2v[r][2] = v0.z; d2v[r][3] = v0.w;
        d2v[r][4] = v1.x; d2v[r][5] = v1.y; d2v[r][6] = v1.z; d2v[r][7] = v1.w;
    }

    float sacc[8];
#pragma unroll
    for (int j = 0; j < 8; j++) sacc[j] = 0.0f;
    float sumA2 = 0.0f;
    float cnt   = 0.0f;

#pragma unroll
    for (int r = 0; r < 8; r++){
        float ss = 0.0f;
        float mv = 3.4e38f;
        int   mi = 1 << 30;
#pragma unroll
        for (int j = 0; j < 8; j++){
            const int   p = lane * 8 + j;
            const float v = d2v[r][j];
            if (v < mv){ mv = v; mi = p; }        // ascending scan -> first min
            if (p != c) ss = fmaf(v, v, ss);
        }
#pragma unroll
        for (int off = 16; off; off >>= 1){
            ss += __shfl_xor_sync(0xffffffffu, ss, off);
            const float ov = __shfl_xor_sync(0xffffffffu, mv, off);
            const int   oi = __shfl_xor_sync(0xffffffffu, mi, off);
            if (ov < mv || (ov == mv && oi < mi)){ mv = ov; mi = oi; }
        }
        const float inv = 1.0f / fmaxf(sqrtf(ss), EPSF);
#pragma unroll
        for (int j = 0; j < 8; j++){
            const int p = lane * 8 + j;
            if (p != c) sacc[j] = fmaf(d2v[r][j], inv, sacc[j]);
        }
        if (lane == 0){
            sumA2 += ss * inv * inv;
            if (mi == c) cnt += 1.0f;
        }
    }

#pragma unroll
    for (int j = 0; j < 8; j++) s_part[w][lane * 8 + j] = sacc[j];
    if (lane == 0){
        atomicAdd(&s_scal[0], sumA2);
        atomicAdd(&s_scal[1], cnt);
    }
    __syncthreads();

    // ||sum_q a_q||^2: column-sum over 8 warps then square-reduce
    float col = 0.0f;
#pragma unroll
    for (int w2 = 0; w2 < 8; w2++) col += s_part[w2][tid];
    float sq = col * col;
#pragma unroll
    for (int off = 16; off; off >>= 1) sq += __shfl_xor_sync(0xffffffffu, sq, off);
    if (lane == 0) s_red[w] = sq;
    __syncthreads();
    if (tid == 0){
        float S2 = 0.0f;
#pragma unroll
        for (int i = 0; i < 8; i++) S2 += s_red[i];
        atomicAdd(&g_cos_sum, 0.5f * (S2 - s_scal[0]));
        atomicAdd(&g_acc_cnt, s_scal[1]);
    }
}

// ---------------- K5: finalize -------------------------------------------
__global__ void k_final(float* __restrict__ out){
    if (threadIdx.x == 0){
        out[0] = g_cos_sum / (float)NPAIRS;
        out[1] = g_acc_cnt / (float)CQ;
    }
}

// ---------------- launch ---------------------------------------------------
extern "C" void kernel_launch(void* const* d_in, const int* in_sizes, int n_in,
                              void* d_out, int out_size){
    const float* xs = (const float*)d_in[0];
    const float* xq = (const float*)d_in[1];
    const float* W  = (const float*)d_in[2];
    float* out = (float*)d_out;
    (void)in_sizes; (void)n_in; (void)out_size;

    k_init<<<1, 1>>>();
    k_gemm<<<M_TOT / 128, 256>>>(xs, xq, W);
    k_proto<<<C_CLS, 128>>>();
    k_d2<<<dim3(128, 2), 256>>>();
    k_loo<<<C_CLS, 256>>>();
    k_final<<<1, 1>>>(out);
}